// round 1
// baseline (speedup 1.0000x reference)
#include <cuda_runtime.h>
#include <math.h>

#define BB   16
#define SQL  2048
#define SKL  2048
#define DD   128
#define NROWS (BB * SQL)

// Scratch (allocation-free: __device__ globals)
__device__ float g_rowmax[NROWS];
__device__ float g_rowsum[NROWS];

__global__ void init_rowmax_kernel() {
    int i = blockIdx.x * blockDim.x + threadIdx.x;
    if (i < NROWS) g_rowmax[i] = -INFINITY;
}

__device__ __forceinline__ void atomicMaxF(float* addr, float val) {
    if (val >= 0.0f) atomicMax((int*)addr, __float_as_int(val));
    else             atomicMin((unsigned int*)addr, __float_as_uint(val));
}

// ---------------------------------------------------------------------------
// Kernel 1: S = scale * Q @ K^T, apply mask (0 -> -1e30), write S to attn
// buffer (scratch), accumulate per-row max into g_rowmax.
// Block: 128x128 output tile, 256 threads, 8x8 per thread, BK=16.
// ---------------------------------------------------------------------------
__global__ __launch_bounds__(256) void qk_kernel(
    const float* __restrict__ Q, const float* __restrict__ Km,
    const int* __restrict__ mask, float* __restrict__ S) {
    __shared__ float sQ[16][128];
    __shared__ float sK[16][128];

    const int b  = blockIdx.z;
    const int q0 = blockIdx.y * 128;
    const int k0 = blockIdx.x * 128;
    const float* Qb = Q  + ((size_t)b * SQL + q0) * DD;
    const float* Kb = Km + ((size_t)b * SKL + k0) * DD;

    const int tid = threadIdx.x;
    const int tx  = tid & 15;
    const int ty  = tid >> 4;

    float acc[8][8];
#pragma unroll
    for (int i = 0; i < 8; i++)
#pragma unroll
        for (int j = 0; j < 8; j++) acc[i][j] = 0.0f;

    for (int kk = 0; kk < DD; kk += 16) {
#pragma unroll
        for (int t = 0; t < 2; t++) {
            int idx = tid + t * 256;      // 0..511
            int row = idx >> 2;           // 0..127
            int c4  = (idx & 3) * 4;      // 0,4,8,12
            float4 qv = *(const float4*)(Qb + (size_t)row * DD + kk + c4);
            sQ[c4 + 0][row] = qv.x;
            sQ[c4 + 1][row] = qv.y;
            sQ[c4 + 2][row] = qv.z;
            sQ[c4 + 3][row] = qv.w;
            float4 kv = *(const float4*)(Kb + (size_t)row * DD + kk + c4);
            sK[c4 + 0][row] = kv.x;
            sK[c4 + 1][row] = kv.y;
            sK[c4 + 2][row] = kv.z;
            sK[c4 + 3][row] = kv.w;
        }
        __syncthreads();
#pragma unroll
        for (int p = 0; p < 16; p++) {
            float4 a0 = *(const float4*)&sQ[p][ty * 8];
            float4 a1 = *(const float4*)&sQ[p][ty * 8 + 4];
            float4 b0 = *(const float4*)&sK[p][tx * 8];
            float4 b1 = *(const float4*)&sK[p][tx * 8 + 4];
            float av[8] = {a0.x, a0.y, a0.z, a0.w, a1.x, a1.y, a1.z, a1.w};
            float bv[8] = {b0.x, b0.y, b0.z, b0.w, b1.x, b1.y, b1.z, b1.w};
#pragma unroll
            for (int i = 0; i < 8; i++)
#pragma unroll
                for (int j = 0; j < 8; j++)
                    acc[i][j] = fmaf(av[i], bv[j], acc[i][j]);
        }
        __syncthreads();
    }

    const float scale = 0.08838834764831845f;  // 1/sqrt(128)
#pragma unroll
    for (int i = 0; i < 8; i++) {
        const int qrow = q0 + ty * 8 + i;
        const size_t base = ((size_t)b * SQL + qrow) * SKL + k0 + tx * 8;
        int4 m0 = *(const int4*)(mask + base);
        int4 m1 = *(const int4*)(mask + base + 4);
        int mm[8] = {m0.x, m0.y, m0.z, m0.w, m1.x, m1.y, m1.z, m1.w};
        float v[8];
        float rm = -INFINITY;
#pragma unroll
        for (int j = 0; j < 8; j++) {
            float s = acc[i][j] * scale;
            if (mm[j] == 0) s = -1e30f;
            v[j] = s;
            rm = fmaxf(rm, s);
        }
        // reduce row max across the 16 tx lanes (stays inside half-warp)
#pragma unroll
        for (int off = 8; off > 0; off >>= 1)
            rm = fmaxf(rm, __shfl_xor_sync(0xffffffffu, rm, off));
        if (tx == 0) atomicMaxF(&g_rowmax[b * SQL + qrow], rm);

        *(float4*)(S + base)     = make_float4(v[0], v[1], v[2], v[3]);
        *(float4*)(S + base + 4) = make_float4(v[4], v[5], v[6], v[7]);
    }
}

// ---------------------------------------------------------------------------
// Kernel 2: one warp per row: rowsum = sum(exp(s - rowmax))
// ---------------------------------------------------------------------------
__global__ __launch_bounds__(256) void rowsum_kernel(const float* __restrict__ S) {
    const int warp = threadIdx.x >> 5;
    const int lane = threadIdx.x & 31;
    const int row  = blockIdx.x * 8 + warp;
    const float m = g_rowmax[row];
    const float4* srow = (const float4*)(S + (size_t)row * SKL);
    float sum = 0.0f;
#pragma unroll 4
    for (int c = lane; c < SKL / 4; c += 32) {
        float4 v = srow[c];
        sum += __expf(v.x - m) + __expf(v.y - m) +
               __expf(v.z - m) + __expf(v.w - m);
    }
#pragma unroll
    for (int off = 16; off > 0; off >>= 1)
        sum += __shfl_xor_sync(0xffffffffu, sum, off);
    if (lane == 0) g_rowsum[row] = sum;
}

// ---------------------------------------------------------------------------
// Kernel 3: P = exp(S - m) / rowsum written in-place over S; ctx = P @ V.
// Block: 128 q-rows x 128 v-cols, 256 threads, 8x8 per thread, BK=32.
// ---------------------------------------------------------------------------
__global__ __launch_bounds__(256) void pv_kernel(
    const float* __restrict__ V, float* __restrict__ S,
    float* __restrict__ ctx) {
    __shared__ float sP[32][128];
    __shared__ float sV[32][128];
    __shared__ float sM[128];
    __shared__ float sI[128];

    const int b  = blockIdx.y;
    const int q0 = blockIdx.x * 128;
    const int tid = threadIdx.x;
    const int tx  = tid & 15;
    const int ty  = tid >> 4;

    if (tid < 128) {
        int r = b * SQL + q0 + tid;
        sM[tid] = g_rowmax[r];
        sI[tid] = 1.0f / g_rowsum[r];
    }
    __syncthreads();

    float acc[8][8];
#pragma unroll
    for (int i = 0; i < 8; i++)
#pragma unroll
        for (int j = 0; j < 8; j++) acc[i][j] = 0.0f;

    for (int k0 = 0; k0 < SKL; k0 += 32) {
        // P tile: 128 rows x 32 cols; normalize + write back + stage to smem
#pragma unroll
        for (int t = 0; t < 4; t++) {
            int idx = tid + t * 256;    // 0..1023
            int row = idx >> 3;         // 0..127
            int c4  = (idx & 7) * 4;    // 0..28
            float* sp = S + ((size_t)b * SQL + q0 + row) * SKL + k0 + c4;
            float4 v = *(const float4*)sp;
            float m = sM[row], inv = sI[row];
            float4 p;
            p.x = __expf(v.x - m) * inv;
            p.y = __expf(v.y - m) * inv;
            p.z = __expf(v.z - m) * inv;
            p.w = __expf(v.w - m) * inv;
            *(float4*)sp = p;           // final attn_weights
            sP[c4 + 0][row] = p.x;
            sP[c4 + 1][row] = p.y;
            sP[c4 + 2][row] = p.z;
            sP[c4 + 3][row] = p.w;
        }
        // V tile: 32 rows x 128 cols
#pragma unroll
        for (int t = 0; t < 4; t++) {
            int idx = tid + t * 256;
            int row = idx >> 5;          // 0..31
            int c4  = (idx & 31) * 4;    // 0..124
            float4 v = *(const float4*)(V + ((size_t)b * SKL + k0 + row) * DD + c4);
            *(float4*)(&sV[row][c4]) = v;
        }
        __syncthreads();
#pragma unroll
        for (int p = 0; p < 32; p++) {
            float4 a0 = *(const float4*)&sP[p][ty * 8];
            float4 a1 = *(const float4*)&sP[p][ty * 8 + 4];
            float4 b0 = *(const float4*)&sV[p][tx * 8];
            float4 b1 = *(const float4*)&sV[p][tx * 8 + 4];
            float av[8] = {a0.x, a0.y, a0.z, a0.w, a1.x, a1.y, a1.z, a1.w};
            float bv[8] = {b0.x, b0.y, b0.z, b0.w, b1.x, b1.y, b1.z, b1.w};
#pragma unroll
            for (int i = 0; i < 8; i++)
#pragma unroll
                for (int j = 0; j < 8; j++)
                    acc[i][j] = fmaf(av[i], bv[j], acc[i][j]);
        }
        __syncthreads();
    }

#pragma unroll
    for (int i = 0; i < 8; i++) {
        size_t obase = ((size_t)b * SQL + q0 + ty * 8 + i) * DD + tx * 8;
        *(float4*)(ctx + obase)     = make_float4(acc[i][0], acc[i][1], acc[i][2], acc[i][3]);
        *(float4*)(ctx + obase + 4) = make_float4(acc[i][4], acc[i][5], acc[i][6], acc[i][7]);
    }
}

// ---------------------------------------------------------------------------
extern "C" void kernel_launch(void* const* d_in, const int* in_sizes, int n_in,
                              void* d_out, int out_size) {
    const float* Q    = (const float*)d_in[0];
    const float* K    = (const float*)d_in[1];
    const float* V    = (const float*)d_in[2];
    const int*   mask = (const int*)d_in[3];

    float* ctx  = (float*)d_out;                              // (B,SQ,DV)
    float* attn = (float*)d_out + (size_t)BB * SQL * DD;      // (B,SQ,SK)

    init_rowmax_kernel<<<(NROWS + 255) / 256, 256>>>();
    qk_kernel<<<dim3(SKL / 128, SQL / 128, BB), 256>>>(Q, K, mask, attn);
    rowsum_kernel<<<NROWS / 8, 256>>>(attn);
    pv_kernel<<<dim3(SQL / 128, BB), 256>>>(V, attn, ctx);
}

// round 4
// speedup vs baseline: 1.3113x; 1.3113x over previous
#include <cuda_runtime.h>
#include <cuda_bf16.h>
#include <cstdint>
#include <math.h>

#define BB   16
#define SQL  2048
#define SKL  2048
#define DD   128
#define NROWS (BB * SQL)
#define NTILES 16

// ---------------- scratch (__device__ globals; no allocation) ----------------
__device__ __nv_bfloat16 g_Qh[(size_t)BB * SQL * DD];
__device__ __nv_bfloat16 g_Ql[(size_t)BB * SQL * DD];
__device__ __nv_bfloat16 g_Kh[(size_t)BB * SKL * DD];
__device__ __nv_bfloat16 g_Kl[(size_t)BB * SKL * DD];
__device__ __nv_bfloat16 g_Vth[(size_t)BB * DD * SKL];   // V^T: [b][dv][k]
__device__ __nv_bfloat16 g_Vtl[(size_t)BB * DD * SKL];
__device__ float g_pm[(size_t)NROWS * NTILES];
__device__ float g_ps[(size_t)NROWS * NTILES];
__device__ float g_rowmax[NROWS];
__device__ float g_rowinv[NROWS];

// ---------------- helpers ----------------------------------------------------
__device__ __forceinline__ uint32_t pack2_hi(float a, float b, float& la, float& lb) {
    __nv_bfloat16 ha = __float2bfloat16_rn(a), hb = __float2bfloat16_rn(b);
    la = a - __bfloat162float(ha);
    lb = b - __bfloat162float(hb);
    return (uint32_t)__bfloat16_as_ushort(ha) | ((uint32_t)__bfloat16_as_ushort(hb) << 16);
}
__device__ __forceinline__ uint32_t pack2(float a, float b) {
    __nv_bfloat16 ha = __float2bfloat16_rn(a), hb = __float2bfloat16_rn(b);
    return (uint32_t)__bfloat16_as_ushort(ha) | ((uint32_t)__bfloat16_as_ushort(hb) << 16);
}
__device__ __forceinline__ void mma_bf16(float* c, uint32_t a0, uint32_t a1,
                                         uint32_t a2, uint32_t a3,
                                         uint32_t b0, uint32_t b1) {
    asm volatile(
        "mma.sync.aligned.m16n8k16.row.col.f32.bf16.bf16.f32 "
        "{%0,%1,%2,%3}, {%4,%5,%6,%7}, {%8,%9}, {%0,%1,%2,%3};"
        : "+f"(c[0]), "+f"(c[1]), "+f"(c[2]), "+f"(c[3])
        : "r"(a0), "r"(a1), "r"(a2), "r"(a3), "r"(b0), "r"(b1));
}

// smem tile geometry: 128 rows x 128 bf16 cols, row stride 272 bytes (136 elems)
#define SMS 272
#define TILE_BYTES (128 * SMS)          // 34816
#define OFF_AH 0
#define OFF_AL TILE_BYTES
#define OFF_BH (2 * TILE_BYTES)
#define OFF_BL (3 * TILE_BYTES)
#define OFF_X  (4 * TILE_BYTES)         // 139264: kernel-specific extras
#define STASHW 132                      // floats per stash row

// ---------------------------------------------------------------------------
// prep: split fp32 rows into hi/lo bf16 (row-major, linear)
// ---------------------------------------------------------------------------
__global__ __launch_bounds__(256) void prep_split_kernel(const float* __restrict__ src, int which) {
    __nv_bfloat16* dh = which ? g_Kh : g_Qh;
    __nv_bfloat16* dl = which ? g_Kl : g_Ql;
    size_t idx = (size_t)blockIdx.x * 256 + threadIdx.x;   // 524288 threads, 8 elems each
    const float* p = src + idx * 8;
    float4 f0 = *(const float4*)p, f1 = *(const float4*)(p + 4);
    float l[8];
    uint4 hv, lv;
    hv.x = pack2_hi(f0.x, f0.y, l[0], l[1]);
    hv.y = pack2_hi(f0.z, f0.w, l[2], l[3]);
    hv.z = pack2_hi(f1.x, f1.y, l[4], l[5]);
    hv.w = pack2_hi(f1.z, f1.w, l[6], l[7]);
    lv.x = pack2(l[0], l[1]); lv.y = pack2(l[2], l[3]);
    lv.z = pack2(l[4], l[5]); lv.w = pack2(l[6], l[7]);
    *(uint4*)(dh + idx * 8) = hv;
    *(uint4*)(dl + idx * 8) = lv;
}

// prep: V^T hi/lo: g_Vth[b][n][k] = V[b][k][n]
__global__ __launch_bounds__(256) void prep_vt_kernel(const float* __restrict__ V) {
    int chunk = blockIdx.x, b = blockIdx.y, tid = threadIdx.x;
#pragma unroll
    for (int g = 0; g < 8; g++) {
        int item = tid + g * 256;     // 0..2047
        int r = item & 127;           // n (dv)
        int c8 = item >> 7;           // k-group 0..15
        int k0 = chunk * 128 + c8 * 8;
        float f[8], l[8];
#pragma unroll
        for (int j = 0; j < 8; j++)
            f[j] = V[((size_t)b * SKL + k0 + j) * DD + r];
        uint4 hv, lv;
        hv.x = pack2_hi(f[0], f[1], l[0], l[1]);
        hv.y = pack2_hi(f[2], f[3], l[2], l[3]);
        hv.z = pack2_hi(f[4], f[5], l[4], l[5]);
        hv.w = pack2_hi(f[6], f[7], l[6], l[7]);
        lv.x = pack2(l[0], l[1]); lv.y = pack2(l[2], l[3]);
        lv.z = pack2(l[4], l[5]); lv.w = pack2(l[6], l[7]);
        size_t dst = ((size_t)b * DD + r) * SKL + k0;
        *(uint4*)(g_Vth + dst) = hv;
        *(uint4*)(g_Vtl + dst) = lv;
    }
}

// ---------------------------------------------------------------------------
// qk: S = scale * Q @ K^T (3-term split-bf16 HMMA), mask, per-(row,ktile)
// softmax partials, coalesced S write. grid (16 kt, 16 qt, 16 b), 256 thr.
// ---------------------------------------------------------------------------
#define DYN_QK (OFF_X + 2048 + 2048 + 512)
__global__ __launch_bounds__(256) void qk_mma_kernel(const int* __restrict__ mask,
                                                     float* __restrict__ S) {
    extern __shared__ char sm[];
    const int tid = threadIdx.x, wid = tid >> 5, lane = tid & 31;
    const int wm = wid >> 2, wn = wid & 3;          // 2 x 4 warp grid
    const int kt = blockIdx.x, qt = blockIdx.y, b = blockIdx.z;
    const size_t rowbase = (size_t)b * SQL + qt * 128;

    // stage Q/K hi+lo tiles
    {
        const uint4* srcs[4] = {
            (const uint4*)(g_Qh + (rowbase)*DD), (const uint4*)(g_Ql + (rowbase)*DD),
            (const uint4*)(g_Kh + ((size_t)b * SKL + kt * 128) * DD),
            (const uint4*)(g_Kl + ((size_t)b * SKL + kt * 128) * DD)};
        char* dsts[4] = {sm + OFF_AH, sm + OFF_AL, sm + OFF_BH, sm + OFF_BL};
#pragma unroll
        for (int t = 0; t < 4; t++) {
#pragma unroll
            for (int g = 0; g < 8; g++) {
                int idx = tid + g * 256;         // 2048 uint4 per tile
                int row = idx >> 4, c16 = idx & 15;
                *(uint4*)(dsts[t] + row * SMS + c16 * 16) = srcs[t][idx];
            }
        }
    }
    __syncthreads();

    float acc[4][4][4];
#pragma unroll
    for (int mt = 0; mt < 4; mt++)
#pragma unroll
        for (int nt = 0; nt < 4; nt++)
#pragma unroll
            for (int i = 0; i < 4; i++) acc[mt][nt][i] = 0.0f;

    const char* sAh = sm + OFF_AH; const char* sAl = sm + OFF_AL;
    const char* sBh = sm + OFF_BH; const char* sBl = sm + OFF_BL;
    const int kbq = (lane & 3) * 4;     // byte offset of (lane%4)*2 bf16
    const int rq  = lane >> 2;

#pragma unroll
    for (int ks = 0; ks < 8; ks++) {
        const int kb = ks * 32 + kbq;
        uint32_t bh[4][2], bl[4][2];
#pragma unroll
        for (int nt = 0; nt < 4; nt++) {
            int n = wn * 32 + nt * 8 + rq;
            const char* pb = sBh + n * SMS + kb;
            bh[nt][0] = *(const uint32_t*)pb;
            bh[nt][1] = *(const uint32_t*)(pb + 16);
            const char* pl = sBl + n * SMS + kb;
            bl[nt][0] = *(const uint32_t*)pl;
            bl[nt][1] = *(const uint32_t*)(pl + 16);
        }
#pragma unroll
        for (int mt = 0; mt < 4; mt++) {
            int r = wm * 64 + mt * 16 + rq;
            const char* pa = sAh + r * SMS + kb;
            uint32_t ah0 = *(const uint32_t*)pa;
            uint32_t ah1 = *(const uint32_t*)(pa + 8 * SMS);
            uint32_t ah2 = *(const uint32_t*)(pa + 16);
            uint32_t ah3 = *(const uint32_t*)(pa + 8 * SMS + 16);
            const char* pal = sAl + r * SMS + kb;
            uint32_t al0 = *(const uint32_t*)pal;
            uint32_t al1 = *(const uint32_t*)(pal + 8 * SMS);
            uint32_t al2 = *(const uint32_t*)(pal + 16);
            uint32_t al3 = *(const uint32_t*)(pal + 8 * SMS + 16);
#pragma unroll
            for (int nt = 0; nt < 4; nt++) {
                mma_bf16(acc[mt][nt], ah0, ah1, ah2, ah3, bh[nt][0], bh[nt][1]);
                mma_bf16(acc[mt][nt], al0, al1, al2, al3, bh[nt][0], bh[nt][1]);
                mma_bf16(acc[mt][nt], ah0, ah1, ah2, ah3, bl[nt][0], bl[nt][1]);
            }
        }
    }

    // scale + mask (in regs)
    const float scale = 0.08838834764831845f;
#pragma unroll
    for (int mt = 0; mt < 4; mt++) {
        size_t r1 = rowbase + wm * 64 + mt * 16 + rq;
#pragma unroll
        for (int nt = 0; nt < 4; nt++) {
            int colg = kt * 128 + wn * 32 + nt * 8 + (lane & 3) * 2;
            int2 m1 = *(const int2*)(mask + r1 * SKL + colg);
            int2 m2 = *(const int2*)(mask + (r1 + 8) * SKL + colg);
            float* c = acc[mt][nt];
            c[0] = (m1.x == 0) ? -1e30f : c[0] * scale;
            c[1] = (m1.y == 0) ? -1e30f : c[1] * scale;
            c[2] = (m2.x == 0) ? -1e30f : c[2] * scale;
            c[3] = (m2.y == 0) ? -1e30f : c[3] * scale;
        }
    }

    float* red1 = (float*)(sm + OFF_X);           // [4 wn][128 rows]
    float* red2 = (float*)(sm + OFF_X + 2048);
    float* rmax = (float*)(sm + OFF_X + 4096);    // [128]

    // per-warp row max over its 32 cols
#pragma unroll
    for (int mt = 0; mt < 4; mt++) {
        float x1 = -INFINITY, x2 = -INFINITY;
#pragma unroll
        for (int nt = 0; nt < 4; nt++) {
            x1 = fmaxf(x1, fmaxf(acc[mt][nt][0], acc[mt][nt][1]));
            x2 = fmaxf(x2, fmaxf(acc[mt][nt][2], acc[mt][nt][3]));
        }
#pragma unroll
        for (int off = 1; off <= 2; off <<= 1) {
            x1 = fmaxf(x1, __shfl_xor_sync(0xffffffffu, x1, off));
            x2 = fmaxf(x2, __shfl_xor_sync(0xffffffffu, x2, off));
        }
        if ((lane & 3) == 0) {
            int rl = wm * 64 + mt * 16 + rq;
            red1[wn * 128 + rl] = x1;
            red1[wn * 128 + rl + 8] = x2;
        }
    }
    __syncthreads();
    if (tid < 128) {
        float m = fmaxf(fmaxf(red1[tid], red1[128 + tid]),
                        fmaxf(red1[256 + tid], red1[384 + tid]));
        rmax[tid] = m;
    }
    __syncthreads();

    // exp partial sums + stash s values
    float* stash = (float*)sm;      // aliases tiles (mma done)
#pragma unroll
    for (int mt = 0; mt < 4; mt++) {
        int rl1 = wm * 64 + mt * 16 + rq, rl2 = rl1 + 8;
        float m1 = rmax[rl1], m2 = rmax[rl2];
        float s1 = 0.0f, s2 = 0.0f;
#pragma unroll
        for (int nt = 0; nt < 4; nt++) {
            int cl = wn * 32 + nt * 8 + (lane & 3) * 2;
            float* c = acc[mt][nt];
            s1 += __expf(c[0] - m1) + __expf(c[1] - m1);
            s2 += __expf(c[2] - m2) + __expf(c[3] - m2);
            stash[rl1 * STASHW + cl] = c[0];
            stash[rl1 * STASHW + cl + 1] = c[1];
            stash[rl2 * STASHW + cl] = c[2];
            stash[rl2 * STASHW + cl + 1] = c[3];
        }
#pragma unroll
        for (int off = 1; off <= 2; off <<= 1) {
            s1 += __shfl_xor_sync(0xffffffffu, s1, off);
            s2 += __shfl_xor_sync(0xffffffffu, s2, off);
        }
        if ((lane & 3) == 0) {
            red2[wn * 128 + rl1] = s1;
            red2[wn * 128 + rl2] = s2;
        }
    }
    __syncthreads();
    if (tid < 128) {
        float s = red2[tid] + red2[128 + tid] + red2[256 + tid] + red2[384 + tid];
        size_t row = rowbase + tid;
        g_pm[row * NTILES + kt] = rmax[tid];
        g_ps[row * NTILES + kt] = s;
    }

    // coalesced S write
#pragma unroll
    for (int g = 0; g < 16; g++) {
        int item = tid + g * 256;                 // 4096 float4
        int r = item >> 5, cg = item & 31;
        *(float4*)(S + (rowbase + r) * SKL + kt * 128 + cg * 4) =
            *(const float4*)&stash[r * STASHW + cg * 4];
    }
}

// ---------------------------------------------------------------------------
// combine per-row partials
// ---------------------------------------------------------------------------
__global__ __launch_bounds__(256) void combine_kernel() {
    int row = blockIdx.x * 256 + threadIdx.x;
    float m = -INFINITY;
    float pm[NTILES], ps[NTILES];
#pragma unroll
    for (int i = 0; i < NTILES; i++) {
        pm[i] = g_pm[(size_t)row * NTILES + i];
        ps[i] = g_ps[(size_t)row * NTILES + i];
        m = fmaxf(m, pm[i]);
    }
    float s = 0.0f;
#pragma unroll
    for (int i = 0; i < NTILES; i++) s += ps[i] * __expf(pm[i] - m);
    g_rowmax[row] = m;
    g_rowinv[row] = 1.0f / s;
}

// ---------------------------------------------------------------------------
// pv: P = exp(S - m) * inv in-place (final attn); ctx = P @ V via split-bf16
// HMMA with register accumulators across 16 k-chunks. grid (16 qt, 16 b).
// ---------------------------------------------------------------------------
#define DYN_PV (OFF_X + 512 + 512)
__global__ __launch_bounds__(256) void pv_mma_kernel(float* __restrict__ S,
                                                     float* __restrict__ ctx) {
    extern __shared__ char sm[];
    const int tid = threadIdx.x, wid = tid >> 5, lane = tid & 31;
    const int wm = wid >> 2, wn = wid & 3;
    const int qt = blockIdx.x, b = blockIdx.y;
    const size_t rowbase = (size_t)b * SQL + qt * 128;

    float* sM = (float*)(sm + OFF_X);
    float* sI = (float*)(sm + OFF_X + 512);
    if (tid < 128) {
        sM[tid] = g_rowmax[rowbase + tid];
        sI[tid] = g_rowinv[rowbase + tid];
    }

    float acc[4][4][4];
#pragma unroll
    for (int mt = 0; mt < 4; mt++)
#pragma unroll
        for (int nt = 0; nt < 4; nt++)
#pragma unroll
            for (int i = 0; i < 4; i++) acc[mt][nt][i] = 0.0f;

    const char* sAh = sm + OFF_AH; const char* sAl = sm + OFF_AL;
    const char* sBh = sm + OFF_BH; const char* sBl = sm + OFF_BL;
    const int kbq = (lane & 3) * 4;
    const int rq  = lane >> 2;

    for (int chunk = 0; chunk < 16; chunk++) {
        __syncthreads();   // protect smem tiles from previous iter's reads

        // normalize S chunk -> P (write back), pack hi/lo into A tiles
#pragma unroll 4
        for (int g = 0; g < 16; g++) {
            int item = tid + g * 256;
            int r = item >> 5, cg = item & 31, c = cg * 4;
            float* ap = S + (rowbase + r) * SKL + chunk * 128 + c;
            float4 s4 = *(const float4*)ap;
            float m = sM[r], inv = sI[r];
            float4 p;
            p.x = __expf(s4.x - m) * inv;
            p.y = __expf(s4.y - m) * inv;
            p.z = __expf(s4.z - m) * inv;
            p.w = __expf(s4.w - m) * inv;
            *(float4*)ap = p;
            float l0, l1, l2, l3;
            uint32_t h0 = pack2_hi(p.x, p.y, l0, l1);
            uint32_t h1 = pack2_hi(p.z, p.w, l2, l3);
            *(uint2*)(sm + OFF_AH + r * SMS + c * 2) = make_uint2(h0, h1);
            *(uint2*)(sm + OFF_AL + r * SMS + c * 2) = make_uint2(pack2(l0, l1), pack2(l2, l3));
        }
        // stage V^T chunk
#pragma unroll
        for (int g = 0; g < 8; g++) {
            int idx = tid + g * 256;             // 2048 uint4
            int n = idx >> 4, c16 = idx & 15;
            size_t src = ((size_t)b * DD + n) * SKL + chunk * 128 + c16 * 8;
            *(uint4*)(sm + OFF_BH + n * SMS + c16 * 16) = *(const uint4*)(g_Vth + src);
            *(uint4*)(sm + OFF_BL + n * SMS + c16 * 16) = *(const uint4*)(g_Vtl + src);
        }
        __syncthreads();

#pragma unroll
        for (int ks = 0; ks < 8; ks++) {
            const int kb = ks * 32 + kbq;
            uint32_t bh[4][2], bl[4][2];
#pragma unroll
            for (int nt = 0; nt < 4; nt++) {
                int n = wn * 32 + nt * 8 + rq;
                const char* pb = sBh + n * SMS + kb;
                bh[nt][0] = *(const uint32_t*)pb;
                bh[nt][1] = *(const uint32_t*)(pb + 16);
                const char* pl = sBl + n * SMS + kb;
                bl[nt][0] = *(const uint32_t*)pl;
                bl[nt][1] = *(const uint32_t*)(pl + 16);
            }
#pragma unroll
            for (int mt = 0; mt < 4; mt++) {
                int r = wm * 64 + mt * 16 + rq;
                const char* pa = sAh + r * SMS + kb;
                uint32_t ah0 = *(const uint32_t*)pa;
                uint32_t ah1 = *(const uint32_t*)(pa + 8 * SMS);
                uint32_t ah2 = *(const uint32_t*)(pa + 16);
                uint32_t ah3 = *(const uint32_t*)(pa + 8 * SMS + 16);
                const char* pal = sAl + r * SMS + kb;
                uint32_t al0 = *(const uint32_t*)pal;
                uint32_t al1 = *(const uint32_t*)(pal + 8 * SMS);
                uint32_t al2 = *(const uint32_t*)(pal + 16);
                uint32_t al3 = *(const uint32_t*)(pal + 8 * SMS + 16);
#pragma unroll
                for (int nt = 0; nt < 4; nt++) {
                    mma_bf16(acc[mt][nt], ah0, ah1, ah2, ah3, bh[nt][0], bh[nt][1]);
                    mma_bf16(acc[mt][nt], al0, al1, al2, al3, bh[nt][0], bh[nt][1]);
                    mma_bf16(acc[mt][nt], ah0, ah1, ah2, ah3, bl[nt][0], bl[nt][1]);
                }
            }
        }
    }
    __syncthreads();

    // stash ctx and write coalesced
    float* stash = (float*)sm;
#pragma unroll
    for (int mt = 0; mt < 4; mt++) {
        int rl1 = wm * 64 + mt * 16 + rq, rl2 = rl1 + 8;
#pragma unroll
        for (int nt = 0; nt < 4; nt++) {
            int cl = wn * 32 + nt * 8 + (lane & 3) * 2;
            stash[rl1 * STASHW + cl]     = acc[mt][nt][0];
            stash[rl1 * STASHW + cl + 1] = acc[mt][nt][1];
            stash[rl2 * STASHW + cl]     = acc[mt][nt][2];
            stash[rl2 * STASHW + cl + 1] = acc[mt][nt][3];
        }
    }
    __syncthreads();
#pragma unroll
    for (int g = 0; g < 16; g++) {
        int item = tid + g * 256;
        int r = item >> 5, cg = item & 31;
        *(float4*)(ctx + (rowbase + r) * DD + cg * 4) =
            *(const float4*)&stash[r * STASHW + cg * 4];
    }
}

// ---------------------------------------------------------------------------
extern "C" void kernel_launch(void* const* d_in, const int* in_sizes, int n_in,
                              void* d_out, int out_size) {
    const float* Q    = (const float*)d_in[0];
    const float* K    = (const float*)d_in[1];
    const float* V    = (const float*)d_in[2];
    const int*   mask = (const int*)d_in[3];

    float* ctx  = (float*)d_out;
    float* attn = (float*)d_out + (size_t)BB * SQL * DD;

    static bool attr_done = false;
    if (!attr_done) {
        cudaFuncSetAttribute(qk_mma_kernel, cudaFuncAttributeMaxDynamicSharedMemorySize, DYN_QK);
        cudaFuncSetAttribute(pv_mma_kernel, cudaFuncAttributeMaxDynamicSharedMemorySize, DYN_PV);
        attr_done = true;
    }

    prep_split_kernel<<<2048, 256>>>(Q, 0);
    prep_split_kernel<<<2048, 256>>>(K, 1);
    prep_vt_kernel<<<dim3(16, BB), 256>>>(V);
    qk_mma_kernel<<<dim3(16, 16, BB), 256, DYN_QK>>>(mask, attn);
    combine_kernel<<<NROWS / 256, 256>>>();
    pv_mma_kernel<<<dim3(16, BB), 256, DYN_PV>>>(attn, ctx);
}

// round 5
// speedup vs baseline: 1.7755x; 1.3540x over previous
#include <cuda_runtime.h>
#include <cuda_bf16.h>
#include <cstdint>
#include <math.h>

#define BB   16
#define SQL  2048
#define SKL  2048
#define DD   128
#define NROWS (BB * SQL)
#define NTILES 16

// ---------------- scratch (__device__ globals; no allocation) ----------------
__device__ __nv_bfloat16 g_Qh[(size_t)BB * SQL * DD];
__device__ __nv_bfloat16 g_Ql[(size_t)BB * SQL * DD];
__device__ __nv_bfloat16 g_Kh[(size_t)BB * SKL * DD];
__device__ __nv_bfloat16 g_Kl[(size_t)BB * SKL * DD];
__device__ __nv_bfloat16 g_Vth[(size_t)BB * DD * SKL];   // V^T: [b][dv][k]
__device__ __nv_bfloat16 g_Vtl[(size_t)BB * DD * SKL];
__device__ float g_pm[(size_t)NROWS * NTILES];
__device__ float g_ps[(size_t)NROWS * NTILES];

// ---------------- helpers ----------------------------------------------------
__device__ __forceinline__ uint32_t pack2_hi(float a, float b, float& la, float& lb) {
    __nv_bfloat16 ha = __float2bfloat16_rn(a), hb = __float2bfloat16_rn(b);
    la = a - __bfloat162float(ha);
    lb = b - __bfloat162float(hb);
    return (uint32_t)__bfloat16_as_ushort(ha) | ((uint32_t)__bfloat16_as_ushort(hb) << 16);
}
__device__ __forceinline__ uint32_t pack2(float a, float b) {
    __nv_bfloat16 ha = __float2bfloat16_rn(a), hb = __float2bfloat16_rn(b);
    return (uint32_t)__bfloat16_as_ushort(ha) | ((uint32_t)__bfloat16_as_ushort(hb) << 16);
}
__device__ __forceinline__ void mma_bf16(float* c, uint32_t a0, uint32_t a1,
                                         uint32_t a2, uint32_t a3,
                                         uint32_t b0, uint32_t b1) {
    asm volatile(
        "mma.sync.aligned.m16n8k16.row.col.f32.bf16.bf16.f32 "
        "{%0,%1,%2,%3}, {%4,%5,%6,%7}, {%8,%9}, {%0,%1,%2,%3};"
        : "+f"(c[0]), "+f"(c[1]), "+f"(c[2]), "+f"(c[3])
        : "r"(a0), "r"(a1), "r"(a2), "r"(a3), "r"(b0), "r"(b1));
}

// slice geometry: 128 rows x 64 bf16 cols, row stride 144 bytes (bank-shift 4)
#define SLW 144
#define SLT (128 * SLW)                 // 18432 per slice tile
#define OFF_AH 0
#define OFF_AL SLT
#define OFF_BH (2 * SLT)
#define OFF_BL (3 * SLT)
#define OFF_X  (4 * SLT)                // 73728
#define STASHW 132
#define DYN_QK (OFF_X + 2048 + 2048 + 512)
#define DYN_PV (OFF_X + 512 + 512)

// ---------------------------------------------------------------------------
// prep: split fp32 rows into hi/lo bf16 (row-major, linear)
// ---------------------------------------------------------------------------
__global__ __launch_bounds__(256) void prep_split_kernel(const float* __restrict__ src, int which) {
    __nv_bfloat16* dh = which ? g_Kh : g_Qh;
    __nv_bfloat16* dl = which ? g_Kl : g_Ql;
    size_t idx = (size_t)blockIdx.x * 256 + threadIdx.x;
    const float* p = src + idx * 8;
    float4 f0 = *(const float4*)p, f1 = *(const float4*)(p + 4);
    float l[8];
    uint4 hv, lv;
    hv.x = pack2_hi(f0.x, f0.y, l[0], l[1]);
    hv.y = pack2_hi(f0.z, f0.w, l[2], l[3]);
    hv.z = pack2_hi(f1.x, f1.y, l[4], l[5]);
    hv.w = pack2_hi(f1.z, f1.w, l[6], l[7]);
    lv.x = pack2(l[0], l[1]); lv.y = pack2(l[2], l[3]);
    lv.z = pack2(l[4], l[5]); lv.w = pack2(l[6], l[7]);
    *(uint4*)(dh + idx * 8) = hv;
    *(uint4*)(dl + idx * 8) = lv;
}

__global__ __launch_bounds__(256) void prep_vt_kernel(const float* __restrict__ V) {
    int chunk = blockIdx.x, b = blockIdx.y, tid = threadIdx.x;
#pragma unroll
    for (int g = 0; g < 8; g++) {
        int item = tid + g * 256;
        int r = item & 127;           // n (dv)
        int c8 = item >> 7;           // k-group
        int k0 = chunk * 128 + c8 * 8;
        float f[8], l[8];
#pragma unroll
        for (int j = 0; j < 8; j++)
            f[j] = V[((size_t)b * SKL + k0 + j) * DD + r];
        uint4 hv, lv;
        hv.x = pack2_hi(f[0], f[1], l[0], l[1]);
        hv.y = pack2_hi(f[2], f[3], l[2], l[3]);
        hv.z = pack2_hi(f[4], f[5], l[4], l[5]);
        hv.w = pack2_hi(f[6], f[7], l[6], l[7]);
        lv.x = pack2(l[0], l[1]); lv.y = pack2(l[2], l[3]);
        lv.z = pack2(l[4], l[5]); lv.w = pack2(l[6], l[7]);
        size_t dst = ((size_t)b * DD + r) * SKL + k0;
        *(uint4*)(g_Vth + dst) = hv;
        *(uint4*)(g_Vtl + dst) = lv;
    }
}

// ---------------------------------------------------------------------------
// inner MMA over one staged 64-k slice (4 k16 steps)
// ---------------------------------------------------------------------------
__device__ __forceinline__ void mma_slice(const char* sm, float acc[4][4][4],
                                          int wm, int wn, int lane) {
    const int kbq = (lane & 3) * 4;
    const int rq  = lane >> 2;
#pragma unroll
    for (int ks = 0; ks < 4; ks++) {
        const int kb = ks * 32 + kbq;
        uint32_t bh[4][2], bl[4][2];
#pragma unroll
        for (int nt = 0; nt < 4; nt++) {
            int n = wn * 32 + nt * 8 + rq;
            const char* pb = sm + OFF_BH + n * SLW + kb;
            bh[nt][0] = *(const uint32_t*)pb;
            bh[nt][1] = *(const uint32_t*)(pb + 16);
            const char* pl = sm + OFF_BL + n * SLW + kb;
            bl[nt][0] = *(const uint32_t*)pl;
            bl[nt][1] = *(const uint32_t*)(pl + 16);
        }
#pragma unroll
        for (int mt = 0; mt < 4; mt++) {
            int r = wm * 64 + mt * 16 + rq;
            const char* pa = sm + OFF_AH + r * SLW + kb;
            uint32_t ah0 = *(const uint32_t*)pa;
            uint32_t ah1 = *(const uint32_t*)(pa + 8 * SLW);
            uint32_t ah2 = *(const uint32_t*)(pa + 16);
            uint32_t ah3 = *(const uint32_t*)(pa + 8 * SLW + 16);
            const char* pal = sm + OFF_AL + r * SLW + kb;
            uint32_t al0 = *(const uint32_t*)pal;
            uint32_t al1 = *(const uint32_t*)(pal + 8 * SLW);
            uint32_t al2 = *(const uint32_t*)(pal + 16);
            uint32_t al3 = *(const uint32_t*)(pal + 8 * SLW + 16);
#pragma unroll
            for (int nt = 0; nt < 4; nt++) {
                mma_bf16(acc[mt][nt], ah0, ah1, ah2, ah3, bh[nt][0], bh[nt][1]);
                mma_bf16(acc[mt][nt], al0, al1, al2, al3, bh[nt][0], bh[nt][1]);
                mma_bf16(acc[mt][nt], ah0, ah1, ah2, ah3, bl[nt][0], bl[nt][1]);
            }
        }
    }
}

// ---------------------------------------------------------------------------
// qk: S = scale * Q @ K^T, mask, per-(row,ktile) partials, coalesced S write.
// grid (16 kt, 16 qt, 16 b), 256 threads, 2 CTAs/SM.
// ---------------------------------------------------------------------------
__global__ __launch_bounds__(256, 2) void qk_mma_kernel(const int* __restrict__ mask,
                                                        float* __restrict__ S) {
    extern __shared__ char sm[];
    const int tid = threadIdx.x, wid = tid >> 5, lane = tid & 31;
    const int wm = wid >> 2, wn = wid & 3;
    const int kt = blockIdx.x, qt = blockIdx.y, b = blockIdx.z;
    const size_t rowbase = (size_t)b * SQL + qt * 128;

    float acc[4][4][4];
#pragma unroll
    for (int mt = 0; mt < 4; mt++)
#pragma unroll
        for (int nt = 0; nt < 4; nt++)
#pragma unroll
            for (int i = 0; i < 4; i++) acc[mt][nt][i] = 0.0f;

    const __nv_bfloat16* srcs[4] = {
        g_Qh + rowbase * DD, g_Ql + rowbase * DD,
        g_Kh + ((size_t)b * SKL + kt * 128) * DD,
        g_Kl + ((size_t)b * SKL + kt * 128) * DD};

#pragma unroll
    for (int sl = 0; sl < 2; sl++) {
        // stage 4 slice tiles: rows 0..127, cols sl*64 .. +64
#pragma unroll
        for (int t = 0; t < 4; t++) {
            char* dst = sm + t * SLT;
#pragma unroll
            for (int g = 0; g < 4; g++) {
                int idx = tid + g * 256;       // 1024 uint4
                int row = idx >> 3, c16 = idx & 7;
                *(uint4*)(dst + row * SLW + c16 * 16) =
                    *(const uint4*)(srcs[t] + (size_t)row * DD + sl * 64 + c16 * 8);
            }
        }
        __syncthreads();
        mma_slice(sm, acc, wm, wn, lane);
        __syncthreads();
    }

    // scale + mask (in regs)
    const float scale = 0.08838834764831845f;
#pragma unroll
    for (int mt = 0; mt < 4; mt++) {
        size_t r1 = rowbase + wm * 64 + mt * 16 + (lane >> 2);
#pragma unroll
        for (int nt = 0; nt < 4; nt++) {
            int colg = kt * 128 + wn * 32 + nt * 8 + (lane & 3) * 2;
            int2 m1 = *(const int2*)(mask + r1 * SKL + colg);
            int2 m2 = *(const int2*)(mask + (r1 + 8) * SKL + colg);
            float* c = acc[mt][nt];
            c[0] = (m1.x == 0) ? -1e30f : c[0] * scale;
            c[1] = (m1.y == 0) ? -1e30f : c[1] * scale;
            c[2] = (m2.x == 0) ? -1e30f : c[2] * scale;
            c[3] = (m2.y == 0) ? -1e30f : c[3] * scale;
        }
    }

    float* red1 = (float*)(sm + OFF_X);
    float* red2 = (float*)(sm + OFF_X + 2048);
    float* rmax = (float*)(sm + OFF_X + 4096);
    const int rq = lane >> 2;

#pragma unroll
    for (int mt = 0; mt < 4; mt++) {
        float x1 = -INFINITY, x2 = -INFINITY;
#pragma unroll
        for (int nt = 0; nt < 4; nt++) {
            x1 = fmaxf(x1, fmaxf(acc[mt][nt][0], acc[mt][nt][1]));
            x2 = fmaxf(x2, fmaxf(acc[mt][nt][2], acc[mt][nt][3]));
        }
#pragma unroll
        for (int off = 1; off <= 2; off <<= 1) {
            x1 = fmaxf(x1, __shfl_xor_sync(0xffffffffu, x1, off));
            x2 = fmaxf(x2, __shfl_xor_sync(0xffffffffu, x2, off));
        }
        if ((lane & 3) == 0) {
            int rl = wm * 64 + mt * 16 + rq;
            red1[wn * 128 + rl] = x1;
            red1[wn * 128 + rl + 8] = x2;
        }
    }
    __syncthreads();
    if (tid < 128)
        rmax[tid] = fmaxf(fmaxf(red1[tid], red1[128 + tid]),
                          fmaxf(red1[256 + tid], red1[384 + tid]));
    __syncthreads();

    float* stash = (float*)sm;      // aliases tiles (mma done)
#pragma unroll
    for (int mt = 0; mt < 4; mt++) {
        int rl1 = wm * 64 + mt * 16 + rq, rl2 = rl1 + 8;
        float m1 = rmax[rl1], m2 = rmax[rl2];
        float s1 = 0.0f, s2 = 0.0f;
#pragma unroll
        for (int nt = 0; nt < 4; nt++) {
            int cl = wn * 32 + nt * 8 + (lane & 3) * 2;
            float* c = acc[mt][nt];
            s1 += __expf(c[0] - m1) + __expf(c[1] - m1);
            s2 += __expf(c[2] - m2) + __expf(c[3] - m2);
            stash[rl1 * STASHW + cl] = c[0];
            stash[rl1 * STASHW + cl + 1] = c[1];
            stash[rl2 * STASHW + cl] = c[2];
            stash[rl2 * STASHW + cl + 1] = c[3];
        }
#pragma unroll
        for (int off = 1; off <= 2; off <<= 1) {
            s1 += __shfl_xor_sync(0xffffffffu, s1, off);
            s2 += __shfl_xor_sync(0xffffffffu, s2, off);
        }
        if ((lane & 3) == 0) {
            red2[wn * 128 + rl1] = s1;
            red2[wn * 128 + rl2] = s2;
        }
    }
    __syncthreads();
    if (tid < 128) {
        float s = red2[tid] + red2[128 + tid] + red2[256 + tid] + red2[384 + tid];
        size_t row = rowbase + tid;
        g_pm[row * NTILES + kt] = rmax[tid];
        g_ps[row * NTILES + kt] = s;
    }

#pragma unroll
    for (int g = 0; g < 16; g++) {
        int item = tid + g * 256;
        int r = item >> 5, cg = item & 31;
        *(float4*)(S + (rowbase + r) * SKL + kt * 128 + cg * 4) =
            *(const float4*)&stash[r * STASHW + cg * 4];
    }
}

// ---------------------------------------------------------------------------
// pv: combine row stats (prologue), P = exp(S-m)*inv in-place (final attn),
// ctx = P @ V, register accs across all 32 k-slices. grid (16 qt, 16 b).
// ---------------------------------------------------------------------------
__global__ __launch_bounds__(256, 2) void pv_mma_kernel(float* __restrict__ S,
                                                        float* __restrict__ ctx) {
    extern __shared__ char sm[];
    const int tid = threadIdx.x, wid = tid >> 5, lane = tid & 31;
    const int wm = wid >> 2, wn = wid & 3;
    const int qt = blockIdx.x, b = blockIdx.y;
    const size_t rowbase = (size_t)b * SQL + qt * 128;

    float* sM = (float*)(sm + OFF_X);
    float* sI = (float*)(sm + OFF_X + 512);
    if (tid < 128) {
        size_t row = rowbase + tid;
        float pm[NTILES], ps[NTILES], m = -INFINITY;
#pragma unroll
        for (int i = 0; i < NTILES; i++) {
            pm[i] = g_pm[row * NTILES + i];
            ps[i] = g_ps[row * NTILES + i];
            m = fmaxf(m, pm[i]);
        }
        float s = 0.0f;
#pragma unroll
        for (int i = 0; i < NTILES; i++) s += ps[i] * __expf(pm[i] - m);
        sM[tid] = m;
        sI[tid] = 1.0f / s;
    }

    float acc[4][4][4];
#pragma unroll
    for (int mt = 0; mt < 4; mt++)
#pragma unroll
        for (int nt = 0; nt < 4; nt++)
#pragma unroll
            for (int i = 0; i < 4; i++) acc[mt][nt][i] = 0.0f;

    for (int half = 0; half < 32; half++) {     // 64-k slices over SKL
        __syncthreads();    // stats ready (first iter) / tiles free (later)
        const int kbase = half * 64;

        // normalize S 128x64 -> P (write back) + pack A hi/lo slice
#pragma unroll
        for (int g = 0; g < 8; g++) {
            int idx = tid + g * 256;            // 2048 float4
            int r = idx >> 4, cg = idx & 15, c = cg * 4;
            float* ap = S + (rowbase + r) * SKL + kbase + c;
            float4 s4 = *(const float4*)ap;
            float m = sM[r], inv = sI[r];
            float4 p;
            p.x = __expf(s4.x - m) * inv;
            p.y = __expf(s4.y - m) * inv;
            p.z = __expf(s4.z - m) * inv;
            p.w = __expf(s4.w - m) * inv;
            *(float4*)ap = p;
            float l0, l1, l2, l3;
            uint32_t h0 = pack2_hi(p.x, p.y, l0, l1);
            uint32_t h1 = pack2_hi(p.z, p.w, l2, l3);
            *(uint2*)(sm + OFF_AH + r * SLW + c * 2) = make_uint2(h0, h1);
            *(uint2*)(sm + OFF_AL + r * SLW + c * 2) = make_uint2(pack2(l0, l1), pack2(l2, l3));
        }
        // stage V^T hi/lo slices: [n 0..127][64 k]
#pragma unroll
        for (int g = 0; g < 4; g++) {
            int idx = tid + g * 256;            // 1024 uint4
            int n = idx >> 3, c16 = idx & 7;
            size_t src = ((size_t)b * DD + n) * SKL + kbase + c16 * 8;
            *(uint4*)(sm + OFF_BH + n * SLW + c16 * 16) = *(const uint4*)(g_Vth + src);
            *(uint4*)(sm + OFF_BL + n * SLW + c16 * 16) = *(const uint4*)(g_Vtl + src);
        }
        __syncthreads();
        mma_slice(sm, acc, wm, wn, lane);
    }
    __syncthreads();

    float* stash = (float*)sm;
    const int rq = lane >> 2;
#pragma unroll
    for (int mt = 0; mt < 4; mt++) {
        int rl1 = wm * 64 + mt * 16 + rq, rl2 = rl1 + 8;
#pragma unroll
        for (int nt = 0; nt < 4; nt++) {
            int cl = wn * 32 + nt * 8 + (lane & 3) * 2;
            stash[rl1 * STASHW + cl]     = acc[mt][nt][0];
            stash[rl1 * STASHW + cl + 1] = acc[mt][nt][1];
            stash[rl2 * STASHW + cl]     = acc[mt][nt][2];
            stash[rl2 * STASHW + cl + 1] = acc[mt][nt][3];
        }
    }
    __syncthreads();
#pragma unroll
    for (int g = 0; g < 16; g++) {
        int item = tid + g * 256;
        int r = item >> 5, cg = item & 31;
        *(float4*)(ctx + (rowbase + r) * DD + cg * 4) =
            *(const float4*)&stash[r * STASHW + cg * 4];
    }
}

// ---------------------------------------------------------------------------
extern "C" void kernel_launch(void* const* d_in, const int* in_sizes, int n_in,
                              void* d_out, int out_size) {
    const float* Q    = (const float*)d_in[0];
    const float* K    = (const float*)d_in[1];
    const float* V    = (const float*)d_in[2];
    const int*   mask = (const int*)d_in[3];

    float* ctx  = (float*)d_out;
    float* attn = (float*)d_out + (size_t)BB * SQL * DD;

    static bool attr_done = false;
    if (!attr_done) {
        cudaFuncSetAttribute(qk_mma_kernel, cudaFuncAttributeMaxDynamicSharedMemorySize, DYN_QK);
        cudaFuncSetAttribute(pv_mma_kernel, cudaFuncAttributeMaxDynamicSharedMemorySize, DYN_PV);
        attr_done = true;
    }

    prep_split_kernel<<<2048, 256>>>(Q, 0);
    prep_split_kernel<<<2048, 256>>>(K, 1);
    prep_vt_kernel<<<dim3(16, BB), 256>>>(V);
    qk_mma_kernel<<<dim3(16, 16, BB), 256, DYN_QK>>>(mask, attn);
    pv_mma_kernel<<<dim3(16, BB), 256, DYN_PV>>>(attn, ctx);
}

// round 6
// speedup vs baseline: 2.1444x; 1.2078x over previous
#include <cuda_runtime.h>
#include <cuda_bf16.h>
#include <cstdint>
#include <math.h>

#define BB   16
#define SQL  2048
#define SKL  2048
#define DD   128
#define NROWS (BB * SQL)
#define NTILES 16

// ---------------- scratch (__device__ globals; no allocation) ----------------
__device__ __nv_bfloat16 g_Qh[(size_t)BB * SQL * DD];
__device__ __nv_bfloat16 g_Ql[(size_t)BB * SQL * DD];
__device__ __nv_bfloat16 g_Kh[(size_t)BB * SKL * DD];
__device__ __nv_bfloat16 g_Kl[(size_t)BB * SKL * DD];
__device__ __nv_bfloat16 g_Vth[(size_t)BB * DD * SKL];   // V^T: [b][dv][k]
__device__ __nv_bfloat16 g_Vtl[(size_t)BB * DD * SKL];
__device__ float g_ps[(size_t)NROWS * NTILES];           // per-(row,ktile) sum exp

// ---------------- helpers ----------------------------------------------------
__device__ __forceinline__ uint32_t pack2_hi(float a, float b, float& la, float& lb) {
    __nv_bfloat16 ha = __float2bfloat16_rn(a), hb = __float2bfloat16_rn(b);
    la = a - __bfloat162float(ha);
    lb = b - __bfloat162float(hb);
    return (uint32_t)__bfloat16_as_ushort(ha) | ((uint32_t)__bfloat16_as_ushort(hb) << 16);
}
__device__ __forceinline__ uint32_t pack2(float a, float b) {
    __nv_bfloat16 ha = __float2bfloat16_rn(a), hb = __float2bfloat16_rn(b);
    return (uint32_t)__bfloat16_as_ushort(ha) | ((uint32_t)__bfloat16_as_ushort(hb) << 16);
}
__device__ __forceinline__ void mma_bf16(float* c, uint32_t a0, uint32_t a1,
                                         uint32_t a2, uint32_t a3,
                                         uint32_t b0, uint32_t b1) {
    asm volatile(
        "mma.sync.aligned.m16n8k16.row.col.f32.bf16.bf16.f32 "
        "{%0,%1,%2,%3}, {%4,%5,%6,%7}, {%8,%9}, {%0,%1,%2,%3};"
        : "+f"(c[0]), "+f"(c[1]), "+f"(c[2]), "+f"(c[3])
        : "r"(a0), "r"(a1), "r"(a2), "r"(a3), "r"(b0), "r"(b1));
}
__device__ __forceinline__ void ldsm4(uint32_t& r0, uint32_t& r1, uint32_t& r2,
                                      uint32_t& r3, uint32_t addr) {
    asm volatile("ldmatrix.sync.aligned.m8n8.x4.shared.b16 {%0,%1,%2,%3}, [%4];"
                 : "=r"(r0), "=r"(r1), "=r"(r2), "=r"(r3) : "r"(addr));
}
__device__ __forceinline__ void cpa16(uint32_t dst, const void* src) {
    asm volatile("cp.async.cg.shared.global [%0], [%1], 16;" :: "r"(dst), "l"(src));
}
#define CP_COMMIT() asm volatile("cp.async.commit_group;" ::: "memory")
#define CP_WAIT0()  asm volatile("cp.async.wait_group 0;" ::: "memory")
#define CP_WAIT1()  asm volatile("cp.async.wait_group 1;" ::: "memory")

// slice geometry: 128 rows x 64 bf16 cols, row stride 144 bytes
#define SLW 144
#define SLT (128 * SLW)                 // 18432 per slice tile
#define OFF_AH 0
#define OFF_AL SLT
#define OFF_BH (2 * SLT)
#define OFF_BL (3 * SLT)
#define DYN_QK (4 * SLT)
#define DYN_PV (4 * SLT)

// ---------------------------------------------------------------------------
// prep: split fp32 rows into hi/lo bf16 (row-major, linear)
// ---------------------------------------------------------------------------
__global__ __launch_bounds__(256) void prep_split_kernel(const float* __restrict__ src, int which) {
    __nv_bfloat16* dh = which ? g_Kh : g_Qh;
    __nv_bfloat16* dl = which ? g_Kl : g_Ql;
    size_t idx = (size_t)blockIdx.x * 256 + threadIdx.x;
    const float* p = src + idx * 8;
    float4 f0 = *(const float4*)p, f1 = *(const float4*)(p + 4);
    float l[8];
    uint4 hv, lv;
    hv.x = pack2_hi(f0.x, f0.y, l[0], l[1]);
    hv.y = pack2_hi(f0.z, f0.w, l[2], l[3]);
    hv.z = pack2_hi(f1.x, f1.y, l[4], l[5]);
    hv.w = pack2_hi(f1.z, f1.w, l[6], l[7]);
    lv.x = pack2(l[0], l[1]); lv.y = pack2(l[2], l[3]);
    lv.z = pack2(l[4], l[5]); lv.w = pack2(l[6], l[7]);
    *(uint4*)(dh + idx * 8) = hv;
    *(uint4*)(dl + idx * 8) = lv;
}

__global__ __launch_bounds__(256) void prep_vt_kernel(const float* __restrict__ V) {
    int chunk = blockIdx.x, b = blockIdx.y, tid = threadIdx.x;
#pragma unroll
    for (int g = 0; g < 8; g++) {
        int item = tid + g * 256;
        int r = item & 127;           // n (dv)
        int c8 = item >> 7;           // k-group
        int k0 = chunk * 128 + c8 * 8;
        float f[8], l[8];
#pragma unroll
        for (int j = 0; j < 8; j++)
            f[j] = V[((size_t)b * SKL + k0 + j) * DD + r];
        uint4 hv, lv;
        hv.x = pack2_hi(f[0], f[1], l[0], l[1]);
        hv.y = pack2_hi(f[2], f[3], l[2], l[3]);
        hv.z = pack2_hi(f[4], f[5], l[4], l[5]);
        hv.w = pack2_hi(f[6], f[7], l[6], l[7]);
        lv.x = pack2(l[0], l[1]); lv.y = pack2(l[2], l[3]);
        lv.z = pack2(l[4], l[5]); lv.w = pack2(l[6], l[7]);
        size_t dst = ((size_t)b * DD + r) * SKL + k0;
        *(uint4*)(g_Vth + dst) = hv;
        *(uint4*)(g_Vtl + dst) = lv;
    }
}

// ---------------------------------------------------------------------------
// qk: E = exp(scale * Q @ K^T) masked (masked -> 0), write E to S buffer,
// per-(row,ktile) partial sums. grid (16 kt, 16 qt, 16 b), 256 thr, 2 CTA/SM.
// ---------------------------------------------------------------------------
__global__ __launch_bounds__(256, 2) void qk_mma_kernel(const int* __restrict__ mask,
                                                        float* __restrict__ S) {
    extern __shared__ char sm[];
    const uint32_t sb = (uint32_t)__cvta_generic_to_shared(sm);
    const int tid = threadIdx.x, wid = tid >> 5, lane = tid & 31;
    const int wm = wid >> 2, wn = wid & 3;
    const int kt = blockIdx.x, qt = blockIdx.y, b = blockIdx.z;
    const size_t rowbase = (size_t)b * SQL + qt * 128;

    // ldmatrix lane address offsets
    const int la_row = lane & 15;
    const int la_k   = (lane & 16) ? 16 : 0;
    const int lb_row = (lane & 7) + ((lane & 16) ? 8 : 0);
    const int lb_k   = (lane & 8) ? 16 : 0;

    float acc[4][4][4];
#pragma unroll
    for (int mt = 0; mt < 4; mt++)
#pragma unroll
        for (int nt = 0; nt < 4; nt++)
#pragma unroll
            for (int i = 0; i < 4; i++) acc[mt][nt][i] = 0.0f;

    const __nv_bfloat16* srcs[4] = {
        g_Qh + rowbase * DD, g_Ql + rowbase * DD,
        g_Kh + ((size_t)b * SKL + kt * 128) * DD,
        g_Kl + ((size_t)b * SKL + kt * 128) * DD};

#pragma unroll
    for (int sl = 0; sl < 2; sl++) {
        // stage 4 slice tiles via cp.async
#pragma unroll
        for (int t = 0; t < 4; t++) {
            uint32_t dstb = sb + t * SLT;
            const __nv_bfloat16* srcp = srcs[t] + sl * 64;
#pragma unroll
            for (int g = 0; g < 4; g++) {
                int idx = tid + g * 256;
                int row = idx >> 3, c16 = idx & 7;
                cpa16(dstb + row * SLW + c16 * 16, srcp + (size_t)row * DD + c16 * 8);
            }
        }
        CP_COMMIT();
        CP_WAIT0();
        __syncthreads();

#pragma unroll
        for (int ks = 0; ks < 4; ks++) {
            const int kb = ks * 32;
            uint32_t bh[4][2], bl[4][2];
#pragma unroll
            for (int ntp = 0; ntp < 2; ntp++) {
                uint32_t ba = sb + OFF_BH + (uint32_t)(wn * 32 + ntp * 16 + lb_row) * SLW + kb + lb_k;
                ldsm4(bh[2 * ntp][0], bh[2 * ntp][1], bh[2 * ntp + 1][0], bh[2 * ntp + 1][1], ba);
                ldsm4(bl[2 * ntp][0], bl[2 * ntp][1], bl[2 * ntp + 1][0], bl[2 * ntp + 1][1], ba + SLT);
            }
#pragma unroll
            for (int mt = 0; mt < 4; mt++) {
                uint32_t aa = sb + OFF_AH + (uint32_t)(wm * 64 + mt * 16 + la_row) * SLW + kb + la_k;
                uint32_t ah0, ah1, ah2, ah3, al0, al1, al2, al3;
                ldsm4(ah0, ah1, ah2, ah3, aa);
                ldsm4(al0, al1, al2, al3, aa + SLT);
#pragma unroll
                for (int nt = 0; nt < 4; nt++) {
                    mma_bf16(acc[mt][nt], ah0, ah1, ah2, ah3, bh[nt][0], bh[nt][1]);
                    mma_bf16(acc[mt][nt], al0, al1, al2, al3, bh[nt][0], bh[nt][1]);
                    mma_bf16(acc[mt][nt], ah0, ah1, ah2, ah3, bl[nt][0], bl[nt][1]);
                }
            }
        }
        __syncthreads();
    }

    // epilogue: mask, exp, partial sums, fragment stores of E
    const float scale = 0.08838834764831845f;
    float* red2 = (float*)sm;         // aliases tiles (MMA done)
    const int rq = lane >> 2;

#pragma unroll
    for (int mt = 0; mt < 4; mt++) {
        const int rl1 = wm * 64 + mt * 16 + rq, rl2 = rl1 + 8;
        const size_t r1 = rowbase + rl1;
        float s1 = 0.0f, s2 = 0.0f;
#pragma unroll
        for (int nt = 0; nt < 4; nt++) {
            int colg = kt * 128 + wn * 32 + nt * 8 + (lane & 3) * 2;
            int2 m1 = *(const int2*)(mask + r1 * SKL + colg);
            int2 m2 = *(const int2*)(mask + (r1 + 8) * SKL + colg);
            float* c = acc[mt][nt];
            float e0 = m1.x ? __expf(c[0] * scale) : 0.0f;
            float e1 = m1.y ? __expf(c[1] * scale) : 0.0f;
            float e2 = m2.x ? __expf(c[2] * scale) : 0.0f;
            float e3 = m2.y ? __expf(c[3] * scale) : 0.0f;
            *(float2*)(S + r1 * SKL + colg)       = make_float2(e0, e1);
            *(float2*)(S + (r1 + 8) * SKL + colg) = make_float2(e2, e3);
            s1 += e0 + e1;
            s2 += e2 + e3;
        }
#pragma unroll
        for (int off = 1; off <= 2; off <<= 1) {
            s1 += __shfl_xor_sync(0xffffffffu, s1, off);
            s2 += __shfl_xor_sync(0xffffffffu, s2, off);
        }
        if ((lane & 3) == 0) {
            red2[wn * 128 + rl1] = s1;
            red2[wn * 128 + rl2] = s2;
        }
    }
    __syncthreads();
    if (tid < 128) {
        float s = red2[tid] + red2[128 + tid] + red2[256 + tid] + red2[384 + tid];
        g_ps[(rowbase + tid) * NTILES + kt] = s;
    }
}

// ---------------------------------------------------------------------------
// pv: inv = 1/sum(partials); P = E * inv written in-place (final attn);
// ctx = P @ V with A fragments built in registers from global E loads and
// double-buffered V^T in smem. grid (16 qt, 16 b), 256 thr, 2 CTA/SM.
// ---------------------------------------------------------------------------
__global__ __launch_bounds__(256, 2) void pv_mma_kernel(float* __restrict__ S,
                                                        float* __restrict__ ctx) {
    extern __shared__ char sm[];
    const uint32_t sb = (uint32_t)__cvta_generic_to_shared(sm);
    const int tid = threadIdx.x, w = tid >> 5, lane = tid & 31;
    const int rq = lane >> 2, qq = (lane & 3) * 2;
    const int qt = blockIdx.x, b = blockIdx.y;
    const size_t rowbase = (size_t)b * SQL + qt * 128;
    const size_t grow1 = rowbase + w * 16 + rq;
    const size_t grow2 = grow1 + 8;

    const int lb_row = (lane & 7) + ((lane & 16) ? 8 : 0);
    const int lb_k   = (lane & 8) ? 16 : 0;

    // per-lane row inverses
    float inv1, inv2;
    {
        const float* p1 = g_ps + grow1 * NTILES;
        const float* p2 = g_ps + grow2 * NTILES;
        float s1 = 0.0f, s2 = 0.0f;
#pragma unroll
        for (int i = 0; i < 4; i++) {
            float4 v1 = *(const float4*)(p1 + i * 4);
            float4 v2 = *(const float4*)(p2 + i * 4);
            s1 += v1.x + v1.y + v1.z + v1.w;
            s2 += v2.x + v2.y + v2.z + v2.w;
        }
        inv1 = 1.0f / s1;
        inv2 = 1.0f / s2;
    }

    float acc[16][4];
#pragma unroll
    for (int nt = 0; nt < 16; nt++)
#pragma unroll
        for (int i = 0; i < 4; i++) acc[nt][i] = 0.0f;

    const __nv_bfloat16* vth = g_Vth + (size_t)b * DD * SKL;
    const __nv_bfloat16* vtl = g_Vtl + (size_t)b * DD * SKL;

    // stage slice s into buffer st
    auto stage = [&](int s, int st) {
        uint32_t d0 = sb + (uint32_t)st * 2 * SLT;
#pragma unroll
        for (int g = 0; g < 4; g++) {
            int idx = tid + g * 256;
            int n = idx >> 3, c16 = idx & 7;
            size_t src = (size_t)n * SKL + s * 64 + c16 * 8;
            cpa16(d0 + n * SLW + c16 * 16, vth + src);
            cpa16(d0 + SLT + n * SLW + c16 * 16, vtl + src);
        }
        CP_COMMIT();
    };

    stage(0, 0);
    for (int s = 0; s < 32; s++) {
        if (s < 31) { stage(s + 1, (s + 1) & 1); CP_WAIT1(); }
        else        { CP_WAIT0(); }
        __syncthreads();

        const uint32_t bbase = sb + (uint32_t)(s & 1) * 2 * SLT;
        const int kbase = s * 64;
#pragma unroll
        for (int ks = 0; ks < 4; ks++) {
            const int col = kbase + ks * 16 + qq;
            float2 e00 = *(const float2*)(S + grow1 * SKL + col);
            float2 e01 = *(const float2*)(S + grow1 * SKL + col + 8);
            float2 e10 = *(const float2*)(S + grow2 * SKL + col);
            float2 e11 = *(const float2*)(S + grow2 * SKL + col + 8);
            float2 p00 = make_float2(e00.x * inv1, e00.y * inv1);
            float2 p01 = make_float2(e01.x * inv1, e01.y * inv1);
            float2 p10 = make_float2(e10.x * inv2, e10.y * inv2);
            float2 p11 = make_float2(e11.x * inv2, e11.y * inv2);
            *(float2*)(S + grow1 * SKL + col)     = p00;
            *(float2*)(S + grow1 * SKL + col + 8) = p01;
            *(float2*)(S + grow2 * SKL + col)     = p10;
            *(float2*)(S + grow2 * SKL + col + 8) = p11;

            float l0, l1;
            uint32_t ah0 = pack2_hi(p00.x, p00.y, l0, l1);
            uint32_t al0 = pack2(l0, l1);
            uint32_t ah1 = pack2_hi(p10.x, p10.y, l0, l1);
            uint32_t al1 = pack2(l0, l1);
            uint32_t ah2 = pack2_hi(p01.x, p01.y, l0, l1);
            uint32_t al2 = pack2(l0, l1);
            uint32_t ah3 = pack2_hi(p11.x, p11.y, l0, l1);
            uint32_t al3 = pack2(l0, l1);

#pragma unroll
            for (int ntp = 0; ntp < 8; ntp++) {
                uint32_t ba = bbase + (uint32_t)(ntp * 16 + lb_row) * SLW + ks * 32 + lb_k;
                uint32_t bh0, bh1, bh2, bh3, bl0, bl1, bl2, bl3;
                ldsm4(bh0, bh1, bh2, bh3, ba);
                ldsm4(bl0, bl1, bl2, bl3, ba + SLT);
                mma_bf16(acc[2 * ntp], ah0, ah1, ah2, ah3, bh0, bh1);
                mma_bf16(acc[2 * ntp], al0, al1, al2, al3, bh0, bh1);
                mma_bf16(acc[2 * ntp], ah0, ah1, ah2, ah3, bl0, bl1);
                mma_bf16(acc[2 * ntp + 1], ah0, ah1, ah2, ah3, bh2, bh3);
                mma_bf16(acc[2 * ntp + 1], al0, al1, al2, al3, bh2, bh3);
                mma_bf16(acc[2 * ntp + 1], ah0, ah1, ah2, ah3, bl2, bl3);
            }
        }
        __syncthreads();
    }

    // ctx written directly from fragments
#pragma unroll
    for (int nt = 0; nt < 16; nt++) {
        int cg = nt * 8 + qq;
        *(float2*)(ctx + grow1 * DD + cg) = make_float2(acc[nt][0], acc[nt][1]);
        *(float2*)(ctx + grow2 * DD + cg) = make_float2(acc[nt][2], acc[nt][3]);
    }
}

// ---------------------------------------------------------------------------
extern "C" void kernel_launch(void* const* d_in, const int* in_sizes, int n_in,
                              void* d_out, int out_size) {
    const float* Q    = (const float*)d_in[0];
    const float* K    = (const float*)d_in[1];
    const float* V    = (const float*)d_in[2];
    const int*   mask = (const int*)d_in[3];

    float* ctx  = (float*)d_out;
    float* attn = (float*)d_out + (size_t)BB * SQL * DD;

    static bool attr_done = false;
    if (!attr_done) {
        cudaFuncSetAttribute(qk_mma_kernel, cudaFuncAttributeMaxDynamicSharedMemorySize, DYN_QK);
        cudaFuncSetAttribute(pv_mma_kernel, cudaFuncAttributeMaxDynamicSharedMemorySize, DYN_PV);
        attr_done = true;
    }

    prep_split_kernel<<<2048, 256>>>(Q, 0);
    prep_split_kernel<<<2048, 256>>>(K, 1);
    prep_vt_kernel<<<dim3(16, BB), 256>>>(V);
    qk_mma_kernel<<<dim3(16, 16, BB), 256, DYN_QK>>>(mask, attn);
    pv_mma_kernel<<<dim3(16, BB), 256, DYN_PV>>>(attn, ctx);
}